// round 14
// baseline (speedup 1.0000x reference)
#include <cuda_runtime.h>
#include <cuda_bf16.h>
#include <cstdint>

// SimCLR supervised-contrastive loss, class-blocked, bf16 mma.sync GEMM.
// (tcgen05 unavailable: harness emits PTX .target sm_103 without 'a'.)
// Pipeline (3 launches):
//  k_sort   - 1 block: counting sort (smem scatter + coalesced writeback),
//             active-tile list, scratch zeroing.
//  k_gather - gather rows to class-sorted bf16 order.
//  k_gemm   - static-stride tile loop, cp.async 3-stage BK=64 mma.sync,
//             symmetric row+col sums. The positive-pair term is harvested
//             FROM THE GRAM TILES: dot(out1_i,out2_i) = G[i, i+B], detected
//             by perm[r]^perm[c]==B (bit-12 pair), counted once per
//             unordered pair (r<c on diagonal tiles). Last finishing block
//             computes the final scalar (no extra launch, no 16MB pos read).

#define NB 8192
#define BHALF 4096
#define D 512
#define D4 (D/4)
#define NC 7
#define TILE 128
#define NTILE (NB/TILE)
#define NPAIR (NTILE*(NTILE+1)/2)   // 2080
#define INV_T 2.0f
#define GEMM_GRID 296

// ---- scratch (__device__ globals; no allocation) ----
__device__ __nv_bfloat16 g_Gh[NB * D];   // class-sorted rows, bf16 (8 MB)
__device__ int   g_perm[NB];
__device__ int   g_labp[NB];
__device__ float g_denom[NB];
__device__ float g_pos;     // sum of dot(out1_i,out2_i), harvested in GEMM
__device__ int   g_ntiles;
__device__ int   g_tiles[NPAIR];
__device__ int   g_done;    // finished-block counter for fused reduce

// ---------------------------------------------------------------------------
// k_sort: 1 block, 1024 threads. Stable counting sort of 8192 labels
// (7 classes) via shuffle scans; smem scatter + coalesced writeback;
// g_labp derived from class boundaries; builds active-tile work list.
__global__ __launch_bounds__(1024) void k_sort(const int* __restrict__ labels) {
    __shared__ int s_perm[NB];          // 32 KB scatter staging
    __shared__ int swtot[NC][32];
    __shared__ int swex[NC][32];
    __shared__ int sctot[NC];
    __shared__ int sbase[NC + 1];
    __shared__ int scnt;
    const int t = threadIdx.x, lane = t & 31, wid = t >> 5;

    int lab[8];
    int cnt[NC];
#pragma unroll
    for (int c = 0; c < NC; c++) cnt[c] = 0;
#pragma unroll
    for (int j = 0; j < 8; j++) {
        lab[j] = labels[t * 8 + j];
#pragma unroll
        for (int c = 0; c < NC; c++) cnt[c] += (lab[j] == c);
    }
    // warp-inclusive scan per class
    int inc[NC];
#pragma unroll
    for (int c = 0; c < NC; c++) {
        int v = cnt[c];
#pragma unroll
        for (int off = 1; off < 32; off <<= 1) {
            int u = __shfl_up_sync(0xffffffffu, v, off);
            if (lane >= off) v += u;
        }
        inc[c] = v;
        if (lane == 31) swtot[c][wid] = v;
    }
#pragma unroll
    for (int j = 0; j < 8; j++) g_denom[t * 8 + j] = 0.0f;
    if (t == 0) { scnt = 0; g_done = 0; g_pos = 0.0f; }
    __syncthreads();
    // cross-warp scan: warp c scans class c over the 32 warp totals
    if (wid < NC) {
        int v = swtot[wid][lane];
        int orig = v;
#pragma unroll
        for (int off = 1; off < 32; off <<= 1) {
            int u = __shfl_up_sync(0xffffffffu, v, off);
            if (lane >= off) v += u;
        }
        swex[wid][lane] = v - orig;
        if (lane == 31) sctot[wid] = v;
    }
    __syncthreads();
    if (t == 0) {
        int run = 0;
#pragma unroll
        for (int c = 0; c < NC; c++) { sbase[c] = run; run += sctot[c]; }
        sbase[NC] = run;   // == NB
    }
    __syncthreads();
    int off_[NC];
#pragma unroll
    for (int c = 0; c < NC; c++)
        off_[c] = sbase[c] + swex[c][wid] + inc[c] - cnt[c];
    // stable replay into SHARED (scattered smem stores are cheap)
#pragma unroll
    for (int j = 0; j < 8; j++) {
#pragma unroll
        for (int c = 0; c < NC; c++) {
            if (lab[j] == c) s_perm[off_[c]++] = t * 8 + j;
        }
    }
    __syncthreads();
    // coalesced writeback; g_labp derived from class boundaries
    for (int p = t; p < NB; p += 1024) {
        g_perm[p] = s_perm[p];
        int c = 0;
#pragma unroll
        for (int k = 1; k < NC; k++) c += (p >= sbase[k]);
        g_labp[p] = c;
    }

    // build active-tile list over upper-triangular (i <= j) tile pairs
    auto classof = [&](int x) {
        int c = 0;
#pragma unroll
        for (int k = 1; k < NC; k++) c += (x >= sbase[k]);
        return c;
    };
    for (int idx = t; idx < NPAIR; idx += 1024) {
        int i = 0, rem = idx;
        while (rem >= NTILE - i) { rem -= NTILE - i; i++; }
        int j = i + rem;
        int rlo = classof(i * TILE), rhi = classof(i * TILE + TILE - 1);
        int clo = classof(j * TILE), chi = classof(j * TILE + TILE - 1);
        if (!(rhi < clo || chi < rlo)) {
            int p = atomicAdd(&scnt, 1);
            g_tiles[p] = (i << 16) | j;
        }
    }
    __syncthreads();
    if (t == 0) g_ntiles = scnt;
}

// ---------------------------------------------------------------------------
// k_gather: gather rows of `out` into class-sorted order, converting to bf16.
#define GPB 1024
__global__ void k_gather(const float* __restrict__ outm) {
    const int b = blockIdx.x, tid = threadIdx.x;
    const int n = NB * D / 8;
    for (int i = b * 256 + tid; i < n; i += GPB * 256) {
        int p = i >> 6;
        int q = i & 63;
        const float4* s =
            reinterpret_cast<const float4*>(outm + (size_t)g_perm[p] * D) + q * 2;
        float4 a = s[0], bb = s[1];
        __nv_bfloat162 h0 = __floats2bfloat162_rn(a.x, a.y);
        __nv_bfloat162 h1 = __floats2bfloat162_rn(a.z, a.w);
        __nv_bfloat162 h2 = __floats2bfloat162_rn(bb.x, bb.y);
        __nv_bfloat162 h3 = __floats2bfloat162_rn(bb.z, bb.w);
        uint4 o;
        o.x = *reinterpret_cast<uint32_t*>(&h0);
        o.y = *reinterpret_cast<uint32_t*>(&h1);
        o.z = *reinterpret_cast<uint32_t*>(&h2);
        o.w = *reinterpret_cast<uint32_t*>(&h3);
        reinterpret_cast<uint4*>(g_Gh)[i] = o;
    }
}

// ---------------------------------------------------------------------------
// mma.sync helpers
__device__ __forceinline__ uint32_t smem_u32(const void* p) {
    uint32_t a;
    asm("{ .reg .u64 t; cvta.to.shared.u64 t, %1; cvt.u32.u64 %0, t; }" : "=r"(a) : "l"(p));
    return a;
}
__device__ __forceinline__ void ldsm_x4(uint32_t* r, uint32_t addr) {
    asm volatile("ldmatrix.sync.aligned.m8n8.x4.shared.b16 {%0,%1,%2,%3}, [%4];"
                 : "=r"(r[0]), "=r"(r[1]), "=r"(r[2]), "=r"(r[3]) : "r"(addr));
}
__device__ __forceinline__ void mma16816(float* d, const uint32_t* a,
                                         uint32_t b0, uint32_t b1) {
    asm volatile(
        "mma.sync.aligned.m16n8k16.row.col.f32.bf16.bf16.f32 "
        "{%0,%1,%2,%3}, {%4,%5,%6,%7}, {%8,%9}, {%0,%1,%2,%3};"
        : "+f"(d[0]), "+f"(d[1]), "+f"(d[2]), "+f"(d[3])
        : "r"(a[0]), "r"(a[1]), "r"(a[2]), "r"(a[3]), "r"(b0), "r"(b1));
}
// 128x64-bf16 tile (128B rows). XOR swizzle: conflict-free for cp.async 16B
// stores and ldmatrix row fetches.
__device__ __forceinline__ uint32_t sw64(int row, int c16) {
    return (uint32_t)(row * 128 + ((c16 ^ (row & 7)) << 4));
}

#define BK 64
#define NKT (D / BK)          // 8
#define STAGE_BYTES 32768     // A 16KB + B 16KB per stage
#define NSTAGE 3

__global__ void __launch_bounds__(256, 2) k_gemm_mma(float* __restrict__ outp) {
    extern __shared__ char dsm[];
    __shared__ float sdenR[TILE];
    __shared__ float sdenC[TILE];
    __shared__ int   slr[TILE], slc[TILE];
    __shared__ int   spr[TILE], spc[TILE];   // perm values for pos detection
    __shared__ float spos;
    __shared__ int   sdone;

    const int tid = threadIdx.x;
    const int wid = tid >> 5, lane = tid & 31;
    const int wm = wid >> 2, wn = wid & 3;        // warp tile 64x32
    const uint4* src = reinterpret_cast<const uint4*>(g_Gh);   // 64 uint4/row
    const uint32_t dyn = smem_u32(dsm);

    const int g = lane >> 3, r8 = lane & 7;
    const int row_off = ((g & 1) << 3) + r8;
    const int cch = g >> 1;
    const int qr = lane >> 2, qc = lane & 3;
    const int ntiles = g_ntiles;

    for (int w = blockIdx.x; w < ntiles; w += GEMM_GRID) {
        const int item = g_tiles[w];
        const int r0 = (item >> 16) * TILE;
        const int c0 = (item & 0xffff) * TILE;
        const bool offdiag = (c0 != r0);

        if (tid < TILE) {
            slr[tid] = g_labp[r0 + tid];
            slc[tid] = g_labp[c0 + tid];
            spr[tid] = g_perm[r0 + tid];
            spc[tid] = g_perm[c0 + tid];
            sdenR[tid] = 0.0f;
            sdenC[tid] = 0.0f;
        }
        if (tid == 0) spos = 0.0f;

        auto issue = [&](int t, int st) {
            const uint32_t sa = dyn + st * STAGE_BYTES;
#pragma unroll
            for (int j = 0; j < 4; j++) {
                int p = j * 256 + tid;
                int row = p >> 3, c16 = p & 7;
                const uint4* gA = src + (size_t)(r0 + row) * 64 + t * 8 + c16;
                const uint4* gB = src + (size_t)(c0 + row) * 64 + t * 8 + c16;
                uint32_t dA = sa + sw64(row, c16);
                uint32_t dB = sa + 16384 + sw64(row, c16);
                asm volatile("cp.async.cg.shared.global [%0], [%1], 16;\n\t"
                             "cp.async.cg.shared.global [%2], [%3], 16;"
                             :: "r"(dA), "l"(gA), "r"(dB), "l"(gB));
            }
            asm volatile("cp.async.commit_group;" ::: "memory");
        };

        issue(0, 0);
        issue(1, 1);

        float acc[4][4][4];
#pragma unroll
        for (int mf = 0; mf < 4; mf++)
#pragma unroll
            for (int nf = 0; nf < 4; nf++)
#pragma unroll
                for (int e = 0; e < 4; e++) acc[mf][nf][e] = 0.0f;

#pragma unroll
        for (int t = 0; t < NKT; t++) {
            if (t < NKT - 1) asm volatile("cp.async.wait_group 1;" ::: "memory");
            else             asm volatile("cp.async.wait_group 0;" ::: "memory");
            __syncthreads();
            if (t + 2 < NKT) issue(t + 2, (t + 2) % NSTAGE);

            const uint32_t sA = dyn + (t % NSTAGE) * STAGE_BYTES;
            const uint32_t sB = sA + 16384;
#pragma unroll
            for (int kc = 0; kc < 4; kc++) {
                uint32_t amat[4][4], bmat[2][4];
                const int c16 = kc * 2 + cch;
#pragma unroll
                for (int mf = 0; mf < 4; mf++)
                    ldsm_x4(amat[mf], sA + sw64(wm * 64 + mf * 16 + row_off, c16));
#pragma unroll
                for (int nb = 0; nb < 2; nb++)
                    ldsm_x4(bmat[nb], sB + sw64(wn * 32 + nb * 16 + row_off, c16));
#pragma unroll
                for (int mf = 0; mf < 4; mf++)
#pragma unroll
                    for (int nf = 0; nf < 4; nf++)
                        mma16816(acc[mf][nf], amat[mf],
                                 bmat[nf >> 1][nf & 1], bmat[nf >> 1][2 + (nf & 1)]);
            }
        }

        // ---- epilogue: mask + exp; row sums always, col sums if offdiag;
        //      harvest positive-pair dots via perm XOR == BHALF ----
        float colsum[4][2];
        float pos_acc = 0.0f;
#pragma unroll
        for (int nf = 0; nf < 4; nf++) { colsum[nf][0] = 0.0f; colsum[nf][1] = 0.0f; }

#pragma unroll
        for (int mf = 0; mf < 4; mf++) {
#pragma unroll
            for (int h = 0; h < 2; h++) {
                const int r = wm * 64 + mf * 16 + h * 8 + qr;
                const int rl = slr[r];
                const int rp = spr[r];
                float rs = 0.0f;
#pragma unroll
                for (int nf = 0; nf < 4; nf++) {
#pragma unroll
                    for (int e = 0; e < 2; e++) {
                        const int c = wn * 32 + nf * 8 + qc * 2 + e;
                        const float v = acc[mf][nf][h * 2 + e];
                        bool ok = (rl == slc[c]) && ((r0 + r) != (c0 + c));
                        float ex = ok ? __expf(INV_T * v) : 0.0f;
                        rs += ex;
                        colsum[nf][e] += ex;
                        // unordered pair {i, i+B}: XOR of original indices
                        // equals BHALF (bit 12). Diagonal tiles see both
                        // orderings -> keep r < c only.
                        if (((rp ^ spc[c]) == BHALF) && (offdiag || r < c))
                            pos_acc += v;
                    }
                }
                rs += __shfl_xor_sync(0xffffffffu, rs, 1);
                rs += __shfl_xor_sync(0xffffffffu, rs, 2);
                if (qc == 0) atomicAdd(&sdenR[r], rs);
            }
        }
        if (offdiag) {
#pragma unroll
            for (int nf = 0; nf < 4; nf++) {
#pragma unroll
                for (int e = 0; e < 2; e++) {
                    float cs = colsum[nf][e];
                    cs += __shfl_xor_sync(0xffffffffu, cs, 4);
                    cs += __shfl_xor_sync(0xffffffffu, cs, 8);
                    cs += __shfl_xor_sync(0xffffffffu, cs, 16);
                    if (qr == 0) {
                        const int c = wn * 32 + nf * 8 + qc * 2 + e;
                        atomicAdd(&sdenC[c], cs);
                    }
                }
            }
        }
        if (pos_acc != 0.0f) atomicAdd(&spos, pos_acc);
        __syncthreads();
        if (tid < TILE) {
            atomicAdd(&g_denom[r0 + tid], sdenR[tid]);
            if (offdiag) atomicAdd(&g_denom[c0 + tid], sdenC[tid]);
        }
        if (tid == 0 && spos != 0.0f) atomicAdd(&g_pos, spos);
        __syncthreads();   // protect smem reuse on next work item
    }

    // ---- last-block final reduction (no separate kernel launch) ----
    __threadfence();
    __syncthreads();
    if (tid == 0) sdone = atomicAdd(&g_done, 1);
    __syncthreads();
    if (sdone == GEMM_GRID - 1) {
        __threadfence();   // acquire: all other blocks' adds visible
        __shared__ float red[8];
        float s = 0.0f;
#pragma unroll
        for (int j = 0; j < NB / 256; j++)
            s += __logf(g_denom[j * 256 + tid]);
#pragma unroll
        for (int off = 16; off > 0; off >>= 1)
            s += __shfl_xor_sync(0xffffffffu, s, off);
        if (lane == 0) red[wid] = s;
        __syncthreads();
        if (wid == 0) {
            float v = (lane < 8) ? red[lane] : 0.0f;
#pragma unroll
            for (int off = 4; off > 0; off >>= 1)
                v += __shfl_xor_sync(0xffffffffu, v, off);
            if (lane == 0)
                outp[0] = v / (float)NB - g_pos * (2.0f * INV_T) / (float)NB;
        }
    }
}

extern "C" void kernel_launch(void* const* d_in, const int* in_sizes, int n_in,
                              void* d_out, int out_size) {
    const float* out_m  = (const float*)d_in[0];   // [2B, D]
    const int*   labels = (const int*)d_in[3];     // [2B]
    float* loss = (float*)d_out;

    cudaFuncSetAttribute(k_gemm_mma, cudaFuncAttributeMaxDynamicSharedMemorySize,
                         NSTAGE * STAGE_BYTES);

    k_sort<<<1, 1024>>>(labels);
    k_gather<<<GPB, 256>>>(out_m);
    k_gemm_mma<<<GEMM_GRID, 256, NSTAGE * STAGE_BYTES>>>(loss);
}

// round 15
// speedup vs baseline: 1.2037x; 1.2037x over previous
#include <cuda_runtime.h>
#include <cuda_bf16.h>
#include <cstdint>

// SimCLR supervised-contrastive loss, class-blocked, bf16 mma.sync GEMM.
// (tcgen05 unavailable: harness emits PTX .target sm_103 without 'a'.)
// Pipeline (4 launches, phase-1 fully parallel):
//  k_hist    - 64 blocks: per-chunk class histograms + g_denom zeroing
//  k_scan    - 1 small block: scan counters, class boundaries, g_labp,
//              active-tile list (direct i,j decode)
//  k_scatgat - 256 blocks: per-chunk stable ranks from smem labels, writes
//              g_perm and streams rows fp32->bf16 DIRECTLY to class-sorted
//              positions (fused scatter+gather; coalesced both sides)
//  k_gemm    - static-stride tile loop, cp.async 3-stage BK=64 mma.sync,
//              symmetric row+col sums, pos term harvested from Gram tiles
//              (perm XOR == B), fused last-block final reduction.

#define NB 8192
#define BHALF 4096
#define D 512
#define D4 (D/4)
#define NC 7
#define CHUNK 128
#define NCHUNK (NB/CHUNK)           // 64
#define TILE 128
#define NTILE (NB/TILE)             // 64
#define NPAIR (NTILE*(NTILE+1)/2)   // 2080
#define INV_T 2.0f
#define GEMM_GRID 296

// ---- scratch (__device__ globals; no allocation) ----
__device__ __nv_bfloat16 g_Gh[NB * D];   // class-sorted rows, bf16 (8 MB)
__device__ int   g_perm[NB];
__device__ int   g_labp[NB];
__device__ int   g_chunkcnt[NCHUNK * NC];
__device__ int   g_chunkbase[NCHUNK * NC];
__device__ float g_denom[NB];
__device__ float g_pos;
__device__ int   g_ntiles;
__device__ int   g_tiles[NPAIR];
__device__ int   g_done;

// ---------------------------------------------------------------------------
// k_hist: 64 blocks x 128. Per-chunk class histogram; zero g_denom.
__global__ __launch_bounds__(128) void k_hist(const int* __restrict__ labels) {
    __shared__ int s[NC];
    const int b = blockIdx.x, t = threadIdx.x;
    if (t < NC) s[t] = 0;
    __syncthreads();
    atomicAdd(&s[labels[b * CHUNK + t]], 1);
    g_denom[b * CHUNK + t] = 0.0f;
    __syncthreads();
    if (t < NC) g_chunkcnt[b * NC + t] = s[t];
}

// ---------------------------------------------------------------------------
// k_scan: 1 block x 1024 (light). Warp c scans class c over 64 chunk counts;
// computes class boundaries; writes g_labp coalesced; builds tile list.
__global__ __launch_bounds__(1024) void k_scan() {
    __shared__ int sex[NCHUNK][NC];
    __shared__ int sctot[NC];
    __shared__ int sbase[NC + 1];
    __shared__ int scnt;
    const int t = threadIdx.x, lane = t & 31, wid = t >> 5;

    if (wid < NC) {
        // chunks 0..31 in v0, 32..63 in v1
        int v0 = g_chunkcnt[lane * NC + wid];
        int v1 = g_chunkcnt[(lane + 32) * NC + wid];
        int o0 = v0, o1 = v1;
#pragma unroll
        for (int off = 1; off < 32; off <<= 1) {
            int u = __shfl_up_sync(0xffffffffu, v0, off);
            if (lane >= off) v0 += u;
            u = __shfl_up_sync(0xffffffffu, v1, off);
            if (lane >= off) v1 += u;
        }
        int tot0 = __shfl_sync(0xffffffffu, v0, 31);
        sex[lane][wid] = v0 - o0;
        sex[lane + 32][wid] = tot0 + v1 - o1;
        if (lane == 31) sctot[wid] = tot0 + v1;
    }
    if (t == 0) { scnt = 0; g_done = 0; g_pos = 0.0f; }
    __syncthreads();
    if (t == 0) {
        int run = 0;
#pragma unroll
        for (int c = 0; c < NC; c++) { sbase[c] = run; run += sctot[c]; }
        sbase[NC] = run;
    }
    __syncthreads();
    if (t < NCHUNK * NC)
        g_chunkbase[t] = sbase[t % NC] + sex[t / NC][t % NC];

    auto classof = [&](int x) {
        int c = 0;
#pragma unroll
        for (int k = 1; k < NC; k++) c += (x >= sbase[k]);
        return c;
    };
    // labp (piecewise constant over class segments), coalesced
    for (int p = t; p < NB; p += 1024) g_labp[p] = classof(p);

    // tile list: direct decode over 64x64, keep j >= i
    for (int idx = t; idx < NTILE * NTILE; idx += 1024) {
        int i = idx >> 6, j = idx & 63;
        if (j < i) continue;
        int rlo = classof(i * TILE), rhi = classof(i * TILE + TILE - 1);
        int clo = classof(j * TILE), chi = classof(j * TILE + TILE - 1);
        if (!(rhi < clo || chi < rlo)) {
            int p = atomicAdd(&scnt, 1);
            g_tiles[p] = (i << 16) | j;
        }
    }
    __syncthreads();
    if (t == 0) g_ntiles = scnt;
}

// ---------------------------------------------------------------------------
// k_scatgat: 256 blocks x 256. Block group (4 per chunk) recomputes the
// chunk's stable ranks from smem labels, writes g_perm (quarter 0 only),
// and streams its 32 rows fp32 -> bf16 to class-sorted destinations.
__global__ __launch_bounds__(256) void k_scatgat(const int* __restrict__ labels,
                                                 const float* __restrict__ outm) {
    __shared__ int slab[CHUNK];
    __shared__ int sdst[CHUNK];
    const int chunk = blockIdx.x >> 2, quarter = blockIdx.x & 3;
    const int tid = threadIdx.x;

    if (tid < CHUNK) slab[tid] = labels[chunk * CHUNK + tid];
    __syncthreads();
    if (tid < CHUNK) {
        int c = slab[tid], rank = 0;
        for (int s = 0; s < tid; s++) rank += (slab[s] == c);
        int dst = g_chunkbase[chunk * NC + c] + rank;
        sdst[tid] = dst;
        if (quarter == 0) g_perm[dst] = chunk * CHUNK + tid;
    }
    __syncthreads();

    // copy rows [quarter*32, quarter*32+32); 64 uint4 (bf16) per row
    uint4* dstG = reinterpret_cast<uint4*>(g_Gh);
#pragma unroll
    for (int k = 0; k < 8; k++) {
        int idx = k * 256 + tid;          // 0..2047 = 32 rows x 64
        int rl = quarter * 32 + (idx >> 6);
        int q = idx & 63;
        const float4* s =
            reinterpret_cast<const float4*>(outm + (size_t)(chunk * CHUNK + rl) * D) + q * 2;
        float4 a = s[0], b = s[1];
        __nv_bfloat162 h0 = __floats2bfloat162_rn(a.x, a.y);
        __nv_bfloat162 h1 = __floats2bfloat162_rn(a.z, a.w);
        __nv_bfloat162 h2 = __floats2bfloat162_rn(b.x, b.y);
        __nv_bfloat162 h3 = __floats2bfloat162_rn(b.z, b.w);
        uint4 o;
        o.x = *reinterpret_cast<uint32_t*>(&h0);
        o.y = *reinterpret_cast<uint32_t*>(&h1);
        o.z = *reinterpret_cast<uint32_t*>(&h2);
        o.w = *reinterpret_cast<uint32_t*>(&h3);
        dstG[(size_t)sdst[rl] * 64 + q] = o;
    }
}

// ---------------------------------------------------------------------------
// mma.sync helpers
__device__ __forceinline__ uint32_t smem_u32(const void* p) {
    uint32_t a;
    asm("{ .reg .u64 t; cvta.to.shared.u64 t, %1; cvt.u32.u64 %0, t; }" : "=r"(a) : "l"(p));
    return a;
}
__device__ __forceinline__ void ldsm_x4(uint32_t* r, uint32_t addr) {
    asm volatile("ldmatrix.sync.aligned.m8n8.x4.shared.b16 {%0,%1,%2,%3}, [%4];"
                 : "=r"(r[0]), "=r"(r[1]), "=r"(r[2]), "=r"(r[3]) : "r"(addr));
}
__device__ __forceinline__ void mma16816(float* d, const uint32_t* a,
                                         uint32_t b0, uint32_t b1) {
    asm volatile(
        "mma.sync.aligned.m16n8k16.row.col.f32.bf16.bf16.f32 "
        "{%0,%1,%2,%3}, {%4,%5,%6,%7}, {%8,%9}, {%0,%1,%2,%3};"
        : "+f"(d[0]), "+f"(d[1]), "+f"(d[2]), "+f"(d[3])
        : "r"(a[0]), "r"(a[1]), "r"(a[2]), "r"(a[3]), "r"(b0), "r"(b1));
}
__device__ __forceinline__ uint32_t sw64(int row, int c16) {
    return (uint32_t)(row * 128 + ((c16 ^ (row & 7)) << 4));
}

#define BK 64
#define NKT (D / BK)          // 8
#define STAGE_BYTES 32768
#define NSTAGE 3

__global__ void __launch_bounds__(256, 2) k_gemm_mma(float* __restrict__ outp) {
    extern __shared__ char dsm[];
    __shared__ float sdenR[TILE];
    __shared__ float sdenC[TILE];
    __shared__ int   slr[TILE], slc[TILE];
    __shared__ int   spr[TILE], spc[TILE];
    __shared__ float spos;
    __shared__ int   sdone;

    const int tid = threadIdx.x;
    const int wid = tid >> 5, lane = tid & 31;
    const int wm = wid >> 2, wn = wid & 3;
    const uint4* src = reinterpret_cast<const uint4*>(g_Gh);
    const uint32_t dyn = smem_u32(dsm);

    const int g = lane >> 3, r8 = lane & 7;
    const int row_off = ((g & 1) << 3) + r8;
    const int cch = g >> 1;
    const int qr = lane >> 2, qc = lane & 3;
    const int ntiles = g_ntiles;

    for (int w = blockIdx.x; w < ntiles; w += GEMM_GRID) {
        const int item = g_tiles[w];
        const int r0 = (item >> 16) * TILE;
        const int c0 = (item & 0xffff) * TILE;
        const bool offdiag = (c0 != r0);

        if (tid < TILE) {
            slr[tid] = g_labp[r0 + tid];
            slc[tid] = g_labp[c0 + tid];
            spr[tid] = g_perm[r0 + tid];
            spc[tid] = g_perm[c0 + tid];
            sdenR[tid] = 0.0f;
            sdenC[tid] = 0.0f;
        }
        if (tid == 0) spos = 0.0f;

        auto issue = [&](int t, int st) {
            const uint32_t sa = dyn + st * STAGE_BYTES;
#pragma unroll
            for (int j = 0; j < 4; j++) {
                int p = j * 256 + tid;
                int row = p >> 3, c16 = p & 7;
                const uint4* gA = src + (size_t)(r0 + row) * 64 + t * 8 + c16;
                const uint4* gB = src + (size_t)(c0 + row) * 64 + t * 8 + c16;
                uint32_t dA = sa + sw64(row, c16);
                uint32_t dB = sa + 16384 + sw64(row, c16);
                asm volatile("cp.async.cg.shared.global [%0], [%1], 16;\n\t"
                             "cp.async.cg.shared.global [%2], [%3], 16;"
                             :: "r"(dA), "l"(gA), "r"(dB), "l"(gB));
            }
            asm volatile("cp.async.commit_group;" ::: "memory");
        };

        issue(0, 0);
        issue(1, 1);

        float acc[4][4][4];
#pragma unroll
        for (int mf = 0; mf < 4; mf++)
#pragma unroll
            for (int nf = 0; nf < 4; nf++)
#pragma unroll
                for (int e = 0; e < 4; e++) acc[mf][nf][e] = 0.0f;

#pragma unroll
        for (int t = 0; t < NKT; t++) {
            if (t < NKT - 1) asm volatile("cp.async.wait_group 1;" ::: "memory");
            else             asm volatile("cp.async.wait_group 0;" ::: "memory");
            __syncthreads();
            if (t + 2 < NKT) issue(t + 2, (t + 2) % NSTAGE);

            const uint32_t sA = dyn + (t % NSTAGE) * STAGE_BYTES;
            const uint32_t sB = sA + 16384;
#pragma unroll
            for (int kc = 0; kc < 4; kc++) {
                uint32_t amat[4][4], bmat[2][4];
                const int c16 = kc * 2 + cch;
#pragma unroll
                for (int mf = 0; mf < 4; mf++)
                    ldsm_x4(amat[mf], sA + sw64(wm * 64 + mf * 16 + row_off, c16));
#pragma unroll
                for (int nb = 0; nb < 2; nb++)
                    ldsm_x4(bmat[nb], sB + sw64(wn * 32 + nb * 16 + row_off, c16));
#pragma unroll
                for (int mf = 0; mf < 4; mf++)
#pragma unroll
                    for (int nf = 0; nf < 4; nf++)
                        mma16816(acc[mf][nf], amat[mf],
                                 bmat[nf >> 1][nf & 1], bmat[nf >> 1][2 + (nf & 1)]);
            }
        }

        // ---- epilogue: mask+exp; row sums; col sums if offdiag; pos harvest
        float colsum[4][2];
        float pos_acc = 0.0f;
#pragma unroll
        for (int nf = 0; nf < 4; nf++) { colsum[nf][0] = 0.0f; colsum[nf][1] = 0.0f; }

#pragma unroll
        for (int mf = 0; mf < 4; mf++) {
#pragma unroll
            for (int h = 0; h < 2; h++) {
                const int r = wm * 64 + mf * 16 + h * 8 + qr;
                const int rl = slr[r];
                const int rp = spr[r];
                float rs = 0.0f;
#pragma unroll
                for (int nf = 0; nf < 4; nf++) {
#pragma unroll
                    for (int e = 0; e < 2; e++) {
                        const int c = wn * 32 + nf * 8 + qc * 2 + e;
                        const float v = acc[mf][nf][h * 2 + e];
                        bool ok = (rl == slc[c]) && ((r0 + r) != (c0 + c));
                        float ex = ok ? __expf(INV_T * v) : 0.0f;
                        rs += ex;
                        colsum[nf][e] += ex;
                        if (((rp ^ spc[c]) == BHALF) && (offdiag || r < c))
                            pos_acc += v;
                    }
                }
                rs += __shfl_xor_sync(0xffffffffu, rs, 1);
                rs += __shfl_xor_sync(0xffffffffu, rs, 2);
                if (qc == 0) atomicAdd(&sdenR[r], rs);
            }
        }
        if (offdiag) {
#pragma unroll
            for (int nf = 0; nf < 4; nf++) {
#pragma unroll
                for (int e = 0; e < 2; e++) {
                    float cs = colsum[nf][e];
                    cs += __shfl_xor_sync(0xffffffffu, cs, 4);
                    cs += __shfl_xor_sync(0xffffffffu, cs, 8);
                    cs += __shfl_xor_sync(0xffffffffu, cs, 16);
                    if (qr == 0) {
                        const int c = wn * 32 + nf * 8 + qc * 2 + e;
                        atomicAdd(&sdenC[c], cs);
                    }
                }
            }
        }
        if (pos_acc != 0.0f) atomicAdd(&spos, pos_acc);
        __syncthreads();
        if (tid < TILE) {
            atomicAdd(&g_denom[r0 + tid], sdenR[tid]);
            if (offdiag) atomicAdd(&g_denom[c0 + tid], sdenC[tid]);
        }
        if (tid == 0 && spos != 0.0f) atomicAdd(&g_pos, spos);
        __syncthreads();
    }

    // ---- last-block final reduction ----
    __threadfence();
    __syncthreads();
    if (tid == 0) sdone = atomicAdd(&g_done, 1);
    __syncthreads();
    if (sdone == GEMM_GRID - 1) {
        __threadfence();
        __shared__ float red[8];
        float s = 0.0f;
#pragma unroll
        for (int j = 0; j < NB / 256; j++)
            s += __logf(g_denom[j * 256 + tid]);
#pragma unroll
        for (int off = 16; off > 0; off >>= 1)
            s += __shfl_xor_sync(0xffffffffu, s, off);
        if (lane == 0) red[wid] = s;
        __syncthreads();
        if (wid == 0) {
            float v = (lane < 8) ? red[lane] : 0.0f;
#pragma unroll
            for (int off = 4; off > 0; off >>= 1)
                v += __shfl_xor_sync(0xffffffffu, v, off);
            if (lane == 0)
                outp[0] = v / (float)NB - g_pos * (2.0f * INV_T) / (float)NB;
        }
    }
}

extern "C" void kernel_launch(void* const* d_in, const int* in_sizes, int n_in,
                              void* d_out, int out_size) {
    const float* out_m  = (const float*)d_in[0];   // [2B, D]
    const int*   labels = (const int*)d_in[3];     // [2B]
    float* loss = (float*)d_out;

    cudaFuncSetAttribute(k_gemm_mma, cudaFuncAttributeMaxDynamicSharedMemorySize,
                         NSTAGE * STAGE_BYTES);

    k_hist<<<NCHUNK, CHUNK>>>(labels);
    k_scan<<<1, 1024>>>();
    k_scatgat<<<256, 256>>>(labels, out_m);
    k_gemm_mma<<<GEMM_GRID, 256, NSTAGE * STAGE_BYTES>>>(loss);
}